// round 2
// baseline (speedup 1.0000x reference)
#include <cuda_runtime.h>
#include <cstdint>

#define BSZ 32
#define NPT 1024
#define NN (BSZ*NPT)      /* 32768 */
#define TOT (2*NN)        /* 65536 */

#define THRESH 0.1f
#define ENT_WT 1e-4

// ------------------------- scratch (device globals; no mallocs) -------------
__device__ float  g_Sr[TOT];
__device__ float  g_Tr[TOT];
__device__ float  g_invSr[TOT];
__device__ float4 g_U4[TOT];
__device__ float  g_Sc[TOT];
__device__ float  g_C[TOT];
__device__ float  g_ssq1[BSZ], g_ssq2[BSZ], g_dot[BSZ];
__device__ float  g_T12[BSZ*12], g_T21[BSZ*12];
__device__ float4 g_pin[TOT];   // mat0: p1in2, mat1: p2in1  (w = |p|^2)
__device__ float4 g_pto[TOT];   // mat0: p1to2, mat1: p2to1  (w = |p|^2)
__device__ double g_acc[6];     // 0 cham, 1 corr, 2 ent2, 3 entG, 4 colterm

// ------------------------- helpers ------------------------------------------
__device__ __forceinline__ float wsum(float v) {
#pragma unroll
    for (int o = 16; o; o >>= 1) v += __shfl_down_sync(0xffffffffu, v, o);
    return v;
}

__device__ __forceinline__ float block_sum(float v, float* sm) {
    int lane = threadIdx.x & 31, w = threadIdx.x >> 5;
    v = wsum(v);
    if (lane == 0) sm[w] = v;
    __syncthreads();
    int nw = (blockDim.x + 31) >> 5;
    v = (threadIdx.x < nw) ? sm[threadIdx.x] : 0.f;
    if (w == 0) v = wsum(v);
    return v;
}

// packed f32x2 helpers (FFMA2 — only reachable via PTX)
__device__ __forceinline__ unsigned long long pk2(float a, float b) {
    unsigned long long r;
    asm("mov.b64 %0, {%1,%2};" : "=l"(r) : "f"(a), "f"(b));
    return r;
}
__device__ __forceinline__ void upk2(unsigned long long v, float& a, float& b) {
    asm("mov.b64 {%0,%1}, %2;" : "=f"(a), "=f"(b) : "l"(v));
}
__device__ __forceinline__ unsigned long long mul2(unsigned long long a, unsigned long long b) {
    unsigned long long d;
    asm("mul.rn.f32x2 %0, %1, %2;" : "=l"(d) : "l"(a), "l"(b));
    return d;
}
__device__ __forceinline__ unsigned long long fma2(unsigned long long a, unsigned long long b,
                                                   unsigned long long c) {
    unsigned long long d;
    asm("fma.rn.f32x2 %0, %1, %2, %3;" : "=l"(d) : "l"(a), "l"(b), "l"(c));
    return d;
}

// ------------------------- init + pose ---------------------------------------
__global__ void k_init(const float* __restrict__ scale,
                       const float* __restrict__ rot,
                       const float* __restrict__ trans) {
    int i = blockIdx.x * 256 + threadIdx.x;
    if (i < TOT) { g_Sc[i] = 0.f; g_C[i] = 0.f; }
    if (i < BSZ) { g_ssq1[i] = 0.f; g_ssq2[i] = 0.f; g_dot[i] = 0.f; }
    if (i < 6)   g_acc[i] = 0.0;

    if (blockIdx.x == 0 && threadIdx.x < BSZ) {
        int b = threadIdx.x;
        float s = scale[b];
        float m[9];
#pragma unroll
        for (int k = 0; k < 9; k++) m[k] = s * rot[b*9 + k];
        float t0 = trans[b*3+0], t1 = trans[b*3+1], t2 = trans[b*3+2];

        float* T = g_T12 + b*12;
        T[0]=m[0]; T[1]=m[1]; T[2]=m[2];  T[3]=t0;
        T[4]=m[3]; T[5]=m[4]; T[6]=m[5];  T[7]=t1;
        T[8]=m[6]; T[9]=m[7]; T[10]=m[8]; T[11]=t2;

        float c00=(m[4]*m[8]-m[5]*m[7]), c01=(m[2]*m[7]-m[1]*m[8]), c02=(m[1]*m[5]-m[2]*m[4]);
        float c10=(m[5]*m[6]-m[3]*m[8]), c11=(m[0]*m[8]-m[2]*m[6]), c12=(m[2]*m[3]-m[0]*m[5]);
        float c20=(m[3]*m[7]-m[4]*m[6]), c21=(m[1]*m[6]-m[0]*m[7]), c22=(m[0]*m[4]-m[1]*m[3]);
        float det = m[0]*c00 + m[1]*c10 + m[2]*c20;
        float id = 1.f/det;
        float i00=c00*id,i01=c01*id,i02=c02*id;
        float i10=c10*id,i11=c11*id,i12=c12*id;
        float i20=c20*id,i21=c21*id,i22=c22*id;
        float u0 = -(i00*t0 + i01*t1 + i02*t2);
        float u1 = -(i10*t0 + i11*t1 + i12*t2);
        float u2 = -(i20*t0 + i21*t1 + i22*t2);
        float* V = g_T21 + b*12;
        V[0]=i00; V[1]=i01; V[2]=i02;  V[3]=u0;
        V[4]=i10; V[5]=i11; V[6]=i12;  V[7]=u1;
        V[8]=i20; V[9]=i21; V[10]=i22; V[11]=u2;
    }
}

// ------------------------- pass 1: row-parallel ------------------------------
// grid (32, 64), 256 threads (8 warps). block covers 16 rows of both matrices;
// warp w handles rows rb*16 + w*2 + {0,1}.
__global__ __launch_bounds__(256, 3)
void k_pass1(const float* __restrict__ A1, const float* __restrict__ A2,
             const float* __restrict__ P1, const float* __restrict__ P2) {
    __shared__ float p1x[NPT], p1y[NPT], p1z[NPT];
    __shared__ float p2x[NPT], p2y[NPT], p2z[NPT];
    __shared__ float rsm[32];

    int b = blockIdx.x;
    int rb = blockIdx.y;
    int tid = threadIdx.x;
    const float* P1g = P1 + (size_t)b*NPT*3;
    const float* P2g = P2 + (size_t)b*NPT*3;
    for (int i = tid; i < NPT; i += 256) {
        p1x[i]=P1g[i*3+0]; p1y[i]=P1g[i*3+1]; p1z[i]=P1g[i*3+2];
        p2x[i]=P2g[i*3+0]; p2y[i]=P2g[i*3+1]; p2z[i]=P2g[i*3+2];
    }
    __syncthreads();

    int warp = tid >> 5, lane = tid & 31;
    int r0 = rb*16 + warp*2;
    const float* A1b = A1 + (size_t)b*NPT*NPT + (size_t)r0*NPT;
    const float* A2b = A2 + (size_t)b*NPT*NPT + (size_t)r0*NPT;

    float ss1 = 0.f, ss2 = 0.f, dp = 0.f;
    float s1[2]={0,0}, t1[2]={0,0}, u1x[2]={0,0}, u1y[2]={0,0}, u1z[2]={0,0};
    float s2[2]={0,0}, t2[2]={0,0}, u2x[2]={0,0}, u2y[2]={0,0}, u2z[2]={0,0};

#pragma unroll
    for (int c = 0; c < 8; c++) {
        int colb = c*128 + lane*4;
        float4 q2x = *(const float4*)&p2x[colb];
        float4 q2y = *(const float4*)&p2y[colb];
        float4 q2z = *(const float4*)&p2z[colb];
        float4 q1x = *(const float4*)&p1x[colb];
        float4 q1y = *(const float4*)&p1y[colb];
        float4 q1z = *(const float4*)&p1z[colb];
#pragma unroll
        for (int r = 0; r < 2; r++) {
            const float4 a1 = *(const float4*)&A1b[(size_t)r*NPT + colb];
            const float4 a2 = *(const float4*)&A2b[(size_t)r*NPT + colb];
#define PROC(cmp) { \
    float a1v=a1.cmp, a2v=a2.cmp; \
    float e1=__expf(a1v), e2=__expf(a2v); \
    s1[r]+=e1; t1[r]=fmaf(e1,a1v,t1[r]); \
    u1x[r]=fmaf(e1,q2x.cmp,u1x[r]); u1y[r]=fmaf(e1,q2y.cmp,u1y[r]); u1z[r]=fmaf(e1,q2z.cmp,u1z[r]); \
    s2[r]+=e2; t2[r]=fmaf(e2,a2v,t2[r]); \
    u2x[r]=fmaf(e2,q1x.cmp,u2x[r]); u2y[r]=fmaf(e2,q1y.cmp,u2y[r]); u2z[r]=fmaf(e2,q1z.cmp,u2z[r]); \
    ss1=fmaf(a1v,a1v,ss1); ss2=fmaf(a2v,a2v,ss2); dp=fmaf(a1v,a2v,dp); }
            PROC(x) PROC(y) PROC(z) PROC(w)
#undef PROC
        }
    }

#pragma unroll
    for (int r = 0; r < 2; r++) {
        int row = r0 + r;
        size_t i1 = (size_t)b*NPT + row;
        size_t i2 = (size_t)NN + i1;
        float vs = wsum(s1[r]);  float vt = wsum(t1[r]);
        float vx = wsum(u1x[r]); float vy = wsum(u1y[r]); float vz = wsum(u1z[r]);
        if (lane == 0) {
            g_Sr[i1]=vs; g_Tr[i1]=vt;
            g_U4[i1] = make_float4(vx, vy, vz, 0.f);
        }
        vs = wsum(s2[r]);  vt = wsum(t2[r]);
        vx = wsum(u2x[r]); vy = wsum(u2y[r]); vz = wsum(u2z[r]);
        if (lane == 0) {
            g_Sr[i2]=vs; g_Tr[i2]=vt;
            g_U4[i2] = make_float4(vx, vy, vz, 0.f);
        }
    }

    float v = block_sum(ss1, rsm);
    if (tid == 0) atomicAdd(&g_ssq1[b], v);
    __syncthreads();
    v = block_sum(ss2, rsm);
    if (tid == 0) atomicAdd(&g_ssq2[b], v);
    __syncthreads();
    v = block_sum(dp, rsm);
    if (tid == 0) atomicAdd(&g_dot[b], v);
}

// ------------------------- row finalize --------------------------------------
__global__ __launch_bounds__(256)
void k_rowfinal(const float* __restrict__ P1, const float* __restrict__ P2) {
    __shared__ float rsm[32];
    int idx = blockIdx.x * 256 + threadIdx.x;   // < 65536
    int mat = idx >> 15;
    int b   = (idx >> 10) & 31;
    int n   = idx & 1023;

    float sr  = g_Sr[idx];
    float isr = 1.f / sr;
    g_invSr[idx] = isr;
    float gq  = g_Tr[idx] * isr;                 // sum_m sa*A for this row
    float e2p = __logf(sr) - gq;

    float4 u = g_U4[idx];
    float px = u.x*isr, py = u.y*isr, pz = u.z*isr;
    g_pin[idx] = make_float4(px, py, pz, px*px+py*py+pz*pz);

    const float* pts = mat ? P2 : P1;
    const float* T   = (mat ? g_T21 : g_T12) + b*12;
    float x0 = pts[((size_t)b*NPT+n)*3+0];
    float x1 = pts[((size_t)b*NPT+n)*3+1];
    float x2 = pts[((size_t)b*NPT+n)*3+2];
    float y0 = T[0]*x0 + T[1]*x1 + T[2]*x2 + T[3];
    float y1 = T[4]*x0 + T[5]*x1 + T[6]*x2 + T[7];
    float y2 = T[8]*x0 + T[9]*x1 + T[10]*x2 + T[11];
    g_pto[idx] = make_float4(y0, y1, y2, y0*y0+y1*y1+y2*y2);

#define HUBER(d) ((d) > THRESH ? (d) - 0.5f*THRESH : (d)*(d)*(0.5f/THRESH))
    float d0 = fabsf(px-y0), d1 = fabsf(py-y1), d2 = fabsf(pz-y2);
    float corr = HUBER(d0) + HUBER(d1) + HUBER(d2);
#undef HUBER

    float v = block_sum(e2p, rsm);
    if (threadIdx.x == 0) atomicAdd(&g_acc[2], (double)v);
    __syncthreads();
    v = block_sum(gq, rsm);
    if (threadIdx.x == 0) atomicAdd(&g_acc[3], (double)v);
    __syncthreads();
    v = block_sum(corr, rsm);
    if (threadIdx.x == 0) atomicAdd(&g_acc[1], (double)v);
}

// ------------------------- pass 2: column-parallel ---------------------------
// grid 256: bx -> rq(4) x b(32) x mat(2). 256 threads, 4 cols each (full width).
__global__ __launch_bounds__(256, 8)
void k_pass2(const float* __restrict__ A1, const float* __restrict__ A2) {
    __shared__ float isr[256];
    int bx = blockIdx.x;
    int rq = bx & 3; int b = (bx >> 2) & 31; int mat = bx >> 7;
    const float* A = (mat ? A2 : A1) + (size_t)b*NPT*NPT;
    int tid = threadIdx.x;
    int row0 = rq * 256;
    isr[tid] = g_invSr[(size_t)(mat*BSZ + b)*NPT + row0 + tid];
    __syncthreads();

    int col = tid*4;
    float sc0=0,sc1=0,sc2=0,sc3=0, c0=0,c1=0,c2=0,c3=0;
#pragma unroll 8
    for (int r = 0; r < 256; r++) {
        float4 a = *(const float4*)&A[(size_t)(row0 + r)*NPT + col];
        float w = isr[r];
        float e;
        e=__expf(a.x); sc0+=e; c0=fmaf(e,w,c0);
        e=__expf(a.y); sc1+=e; c1=fmaf(e,w,c1);
        e=__expf(a.z); sc2+=e; c2=fmaf(e,w,c2);
        e=__expf(a.w); sc3+=e; c3=fmaf(e,w,c3);
    }
    size_t o = (size_t)(mat*BSZ + b)*NPT + col;
    atomicAdd(&g_Sc[o+0], sc0); atomicAdd(&g_Sc[o+1], sc1);
    atomicAdd(&g_Sc[o+2], sc2); atomicAdd(&g_Sc[o+3], sc3);
    atomicAdd(&g_C[o+0], c0);  atomicAdd(&g_C[o+1], c1);
    atomicAdd(&g_C[o+2], c2);  atomicAdd(&g_C[o+3], c3);
}

// ------------------------- column finalize -----------------------------------
__global__ __launch_bounds__(256)
void k_colfinal() {
    __shared__ float rsm[32];
    int i = blockIdx.x * 256 + threadIdx.x;   // < 65536
    float v = __logf(g_Sc[i]) * g_C[i];
    v = block_sum(v, rsm);
    if (threadIdx.x == 0) atomicAdd(&g_acc[4], (double)v);
}

// ------------------------- chamfer (packed f32x2) ----------------------------
// grid 128: bx -> b(32) x dir(2) x prob(2). 512 threads, 2 x-points each.
__global__ __launch_bounds__(512)
void k_chamfer() {
    __shared__ ulonglong2 sYA[NPT/2];   // (x-pair, y-pair)
    __shared__ ulonglong2 sYB[NPT/2];   // (z-pair, w-pair)
    __shared__ float rsm[32];
    int bx = blockIdx.x;
    int b = bx & 31; int dir = (bx >> 5) & 1; int prob = bx >> 6;
    size_t base = (size_t)(prob*BSZ + b) * NPT;
    const float4* X = dir ? (g_pin + base) : (g_pto + base);
    const float4* Y = dir ? (g_pto + base) : (g_pin + base);
    int tid = threadIdx.x;

    {
        float4 y0 = Y[2*tid], y1 = Y[2*tid+1];
        sYA[tid] = make_ulonglong2(pk2(y0.x, y1.x), pk2(y0.y, y1.y));
        sYB[tid] = make_ulonglong2(pk2(y0.z, y1.z), pk2(y0.w, y1.w));
    }
    __syncthreads();

    float4 xa = X[tid];
    float4 xb = X[tid + 512];
    unsigned long long ax = pk2(xa.x, xa.x), ay = pk2(xa.y, xa.y), az = pk2(xa.z, xa.z);
    unsigned long long bx2 = pk2(xb.x, xb.x), by = pk2(xb.y, xb.y), bz = pk2(xb.z, xb.z);
    const unsigned long long neg2 = pk2(-2.f, -2.f);

    float mna = 1e30f, mnb = 1e30f;
#pragma unroll 4
    for (int m = 0; m < NPT/2; m++) {
        ulonglong2 A = sYA[m];
        ulonglong2 B = sYB[m];
        unsigned long long d, v;
        float lo, hi;
        d = mul2(ax, A.x); d = fma2(ay, A.y, d); d = fma2(az, B.x, d);
        v = fma2(neg2, d, B.y);
        upk2(v, lo, hi);
        mna = fminf(mna, fminf(lo, hi));
        d = mul2(bx2, A.x); d = fma2(by, A.y, d); d = fma2(bz, B.x, d);
        v = fma2(neg2, d, B.y);
        upk2(v, lo, hi);
        mnb = fminf(mnb, fminf(lo, hi));
    }
    float dsum = fmaxf(xa.w + mna, 0.f) + fmaxf(xb.w + mnb, 0.f);
    float v = block_sum(dsum, rsm);
    if (tid == 0) atomicAdd(&g_acc[0], (double)v);
}

// ------------------------- final combine -------------------------------------
__global__ void k_final(float* __restrict__ out) {
    int b = threadIdx.x;   // 32 threads
    float n1 = sqrtf(g_ssq1[b]);
    float n2 = sqrtf(g_ssq2[b]);
    float cosv = 1.f - g_dot[b] / (fmaxf(n1, 1e-8f) * fmaxf(n2, 1e-8f));
    cosv = wsum(cosv);
    if (b == 0) {
        double invBN = 1.0 / (double)(BSZ * NPT);
        double total = g_acc[0] * invBN
                     + g_acc[1] * invBN
                     + ENT_WT * invBN * (g_acc[2] + g_acc[4] - g_acc[3])
                     + (double)cosv / (double)BSZ;
        out[0] = (float)total;
    }
}

// ------------------------- launch --------------------------------------------
extern "C" void kernel_launch(void* const* d_in, const int* in_sizes, int n_in,
                              void* d_out, int out_size) {
    const float* P1 = (const float*)d_in[0];
    const float* P2 = (const float*)d_in[1];
    const float* A1 = (const float*)d_in[2];
    const float* A2 = (const float*)d_in[3];
    const float* sc = (const float*)d_in[4];
    const float* rt = (const float*)d_in[5];
    const float* tr = (const float*)d_in[6];
    float* out = (float*)d_out;

    k_init<<<TOT/256, 256>>>(sc, rt, tr);
    k_pass1<<<dim3(BSZ, 64), 256>>>(A1, A2, P1, P2);
    k_rowfinal<<<TOT/256, 256>>>(P1, P2);
    k_pass2<<<256, 256>>>(A1, A2);
    k_colfinal<<<TOT/256, 256>>>();
    k_chamfer<<<128, 512>>>();
    k_final<<<1, 32>>>(out);
}

// round 3
// speedup vs baseline: 1.6219x; 1.6219x over previous
#include <cuda_runtime.h>
#include <cstdint>

#define BSZ 32
#define NPT 1024
#define NN (BSZ*NPT)      /* 32768 */
#define TOT (2*NN)        /* 65536 */

#define THRESH 0.1f
#define ENT_WT 1e-4

// ------------------------- scratch (device globals; no mallocs) -------------
__device__ float  g_Sr[TOT];
__device__ float  g_Tr[TOT];
__device__ float  g_invSr[TOT];
__device__ float4 g_U4[TOT];
__device__ float  g_Sc[TOT];
__device__ float  g_C[TOT];
__device__ float  g_ssq1[BSZ], g_ssq2[BSZ], g_dot[BSZ];
__device__ float  g_T12[BSZ*12], g_T21[BSZ*12];
__device__ float4 g_pin[TOT];   // mat0: p1in2, mat1: p2in1  (w = |p|^2)
__device__ float4 g_pto[TOT];   // mat0: p1to2, mat1: p2to1  (w = |p|^2)
__device__ double g_acc[6];     // 0 cham, 1 corr, 2 ent2, 3 entG, 4 colterm

// ------------------------- helpers ------------------------------------------
__device__ __forceinline__ float wsum(float v) {
#pragma unroll
    for (int o = 16; o; o >>= 1) v += __shfl_down_sync(0xffffffffu, v, o);
    return v;
}

__device__ __forceinline__ float block_sum(float v, float* sm) {
    int lane = threadIdx.x & 31, w = threadIdx.x >> 5;
    v = wsum(v);
    if (lane == 0) sm[w] = v;
    __syncthreads();
    int nw = (blockDim.x + 31) >> 5;
    v = (threadIdx.x < nw) ? sm[threadIdx.x] : 0.f;
    if (w == 0) v = wsum(v);
    return v;
}

// packed f32x2 helpers (FFMA2 — only reachable via PTX)
__device__ __forceinline__ unsigned long long pk2(float a, float b) {
    unsigned long long r;
    asm("mov.b64 %0, {%1,%2};" : "=l"(r) : "f"(a), "f"(b));
    return r;
}
__device__ __forceinline__ void upk2(unsigned long long v, float& a, float& b) {
    asm("mov.b64 {%0,%1}, %2;" : "=f"(a), "=f"(b) : "l"(v));
}
__device__ __forceinline__ unsigned long long mul2(unsigned long long a, unsigned long long b) {
    unsigned long long d;
    asm("mul.rn.f32x2 %0, %1, %2;" : "=l"(d) : "l"(a), "l"(b));
    return d;
}
__device__ __forceinline__ unsigned long long fma2(unsigned long long a, unsigned long long b,
                                                   unsigned long long c) {
    unsigned long long d;
    asm("fma.rn.f32x2 %0, %1, %2, %3;" : "=l"(d) : "l"(a), "l"(b), "l"(c));
    return d;
}

// ------------------------- init + pose ---------------------------------------
__global__ void k_init(const float* __restrict__ scale,
                       const float* __restrict__ rot,
                       const float* __restrict__ trans) {
    int i = blockIdx.x * 256 + threadIdx.x;
    if (i < TOT) { g_Sc[i] = 0.f; g_C[i] = 0.f; }
    if (i < BSZ) { g_ssq1[i] = 0.f; g_ssq2[i] = 0.f; g_dot[i] = 0.f; }
    if (i < 6)   g_acc[i] = 0.0;

    if (blockIdx.x == 0 && threadIdx.x < BSZ) {
        int b = threadIdx.x;
        float s = scale[b];
        float m[9];
#pragma unroll
        for (int k = 0; k < 9; k++) m[k] = s * rot[b*9 + k];
        float t0 = trans[b*3+0], t1 = trans[b*3+1], t2 = trans[b*3+2];

        float* T = g_T12 + b*12;
        T[0]=m[0]; T[1]=m[1]; T[2]=m[2];  T[3]=t0;
        T[4]=m[3]; T[5]=m[4]; T[6]=m[5];  T[7]=t1;
        T[8]=m[6]; T[9]=m[7]; T[10]=m[8]; T[11]=t2;

        float c00=(m[4]*m[8]-m[5]*m[7]), c01=(m[2]*m[7]-m[1]*m[8]), c02=(m[1]*m[5]-m[2]*m[4]);
        float c10=(m[5]*m[6]-m[3]*m[8]), c11=(m[0]*m[8]-m[2]*m[6]), c12=(m[2]*m[3]-m[0]*m[5]);
        float c20=(m[3]*m[7]-m[4]*m[6]), c21=(m[1]*m[6]-m[0]*m[7]), c22=(m[0]*m[4]-m[1]*m[3]);
        float det = m[0]*c00 + m[1]*c10 + m[2]*c20;
        float id = 1.f/det;
        float i00=c00*id,i01=c01*id,i02=c02*id;
        float i10=c10*id,i11=c11*id,i12=c12*id;
        float i20=c20*id,i21=c21*id,i22=c22*id;
        float u0 = -(i00*t0 + i01*t1 + i02*t2);
        float u1 = -(i10*t0 + i11*t1 + i12*t2);
        float u2 = -(i20*t0 + i21*t1 + i22*t2);
        float* V = g_T21 + b*12;
        V[0]=i00; V[1]=i01; V[2]=i02;  V[3]=u0;
        V[4]=i10; V[5]=i11; V[6]=i12;  V[7]=u1;
        V[8]=i20; V[9]=i21; V[10]=i22; V[11]=u2;
    }
}

// ------------------------- pass 1: row-parallel ------------------------------
// grid (32, 64), 256 threads (8 warps). block covers 16 rows of both matrices;
// warp w handles rows rb*16 + w*2 + {0,1}.
__global__ __launch_bounds__(256, 3)
void k_pass1(const float* __restrict__ A1, const float* __restrict__ A2,
             const float* __restrict__ P1, const float* __restrict__ P2) {
    __shared__ float p1x[NPT], p1y[NPT], p1z[NPT];
    __shared__ float p2x[NPT], p2y[NPT], p2z[NPT];
    __shared__ float rsm[32];

    int b = blockIdx.x;
    int rb = blockIdx.y;
    int tid = threadIdx.x;
    const float* P1g = P1 + (size_t)b*NPT*3;
    const float* P2g = P2 + (size_t)b*NPT*3;
    for (int i = tid; i < NPT; i += 256) {
        p1x[i]=P1g[i*3+0]; p1y[i]=P1g[i*3+1]; p1z[i]=P1g[i*3+2];
        p2x[i]=P2g[i*3+0]; p2y[i]=P2g[i*3+1]; p2z[i]=P2g[i*3+2];
    }
    __syncthreads();

    int warp = tid >> 5, lane = tid & 31;
    int r0 = rb*16 + warp*2;
    const float* A1b = A1 + (size_t)b*NPT*NPT + (size_t)r0*NPT;
    const float* A2b = A2 + (size_t)b*NPT*NPT + (size_t)r0*NPT;

    float ss1 = 0.f, ss2 = 0.f, dp = 0.f;
    float s1[2]={0,0}, t1[2]={0,0}, u1x[2]={0,0}, u1y[2]={0,0}, u1z[2]={0,0};
    float s2[2]={0,0}, t2[2]={0,0}, u2x[2]={0,0}, u2y[2]={0,0}, u2z[2]={0,0};

#pragma unroll
    for (int c = 0; c < 8; c++) {
        int colb = c*128 + lane*4;
        float4 q2x = *(const float4*)&p2x[colb];
        float4 q2y = *(const float4*)&p2y[colb];
        float4 q2z = *(const float4*)&p2z[colb];
        float4 q1x = *(const float4*)&p1x[colb];
        float4 q1y = *(const float4*)&p1y[colb];
        float4 q1z = *(const float4*)&p1z[colb];
#pragma unroll
        for (int r = 0; r < 2; r++) {
            const float4 a1 = __ldcs((const float4*)&A1b[(size_t)r*NPT + colb]);
            const float4 a2 = __ldcs((const float4*)&A2b[(size_t)r*NPT + colb]);
#define PROC(cmp) { \
    float a1v=a1.cmp, a2v=a2.cmp; \
    float e1=__expf(a1v), e2=__expf(a2v); \
    s1[r]+=e1; t1[r]=fmaf(e1,a1v,t1[r]); \
    u1x[r]=fmaf(e1,q2x.cmp,u1x[r]); u1y[r]=fmaf(e1,q2y.cmp,u1y[r]); u1z[r]=fmaf(e1,q2z.cmp,u1z[r]); \
    s2[r]+=e2; t2[r]=fmaf(e2,a2v,t2[r]); \
    u2x[r]=fmaf(e2,q1x.cmp,u2x[r]); u2y[r]=fmaf(e2,q1y.cmp,u2y[r]); u2z[r]=fmaf(e2,q1z.cmp,u2z[r]); \
    ss1=fmaf(a1v,a1v,ss1); ss2=fmaf(a2v,a2v,ss2); dp=fmaf(a1v,a2v,dp); }
            PROC(x) PROC(y) PROC(z) PROC(w)
#undef PROC
        }
    }

#pragma unroll
    for (int r = 0; r < 2; r++) {
        int row = r0 + r;
        size_t i1 = (size_t)b*NPT + row;
        size_t i2 = (size_t)NN + i1;
        float vs = wsum(s1[r]);  float vt = wsum(t1[r]);
        float vx = wsum(u1x[r]); float vy = wsum(u1y[r]); float vz = wsum(u1z[r]);
        if (lane == 0) {
            g_Sr[i1]=vs; g_Tr[i1]=vt;
            g_U4[i1] = make_float4(vx, vy, vz, 0.f);
        }
        vs = wsum(s2[r]);  vt = wsum(t2[r]);
        vx = wsum(u2x[r]); vy = wsum(u2y[r]); vz = wsum(u2z[r]);
        if (lane == 0) {
            g_Sr[i2]=vs; g_Tr[i2]=vt;
            g_U4[i2] = make_float4(vx, vy, vz, 0.f);
        }
    }

    float v = block_sum(ss1, rsm);
    if (tid == 0) atomicAdd(&g_ssq1[b], v);
    __syncthreads();
    v = block_sum(ss2, rsm);
    if (tid == 0) atomicAdd(&g_ssq2[b], v);
    __syncthreads();
    v = block_sum(dp, rsm);
    if (tid == 0) atomicAdd(&g_dot[b], v);
}

// ------------------------- row finalize --------------------------------------
__global__ __launch_bounds__(256)
void k_rowfinal(const float* __restrict__ P1, const float* __restrict__ P2) {
    __shared__ float rsm[32];
    int idx = blockIdx.x * 256 + threadIdx.x;   // < 65536
    int mat = idx >> 15;
    int b   = (idx >> 10) & 31;
    int n   = idx & 1023;

    float sr  = g_Sr[idx];
    float isr = 1.f / sr;
    g_invSr[idx] = isr;
    float gq  = g_Tr[idx] * isr;                 // sum_m sa*A for this row
    float e2p = __logf(sr) - gq;

    float4 u = g_U4[idx];
    float px = u.x*isr, py = u.y*isr, pz = u.z*isr;
    g_pin[idx] = make_float4(px, py, pz, px*px+py*py+pz*pz);

    const float* pts = mat ? P2 : P1;
    const float* T   = (mat ? g_T21 : g_T12) + b*12;
    float x0 = pts[((size_t)b*NPT+n)*3+0];
    float x1 = pts[((size_t)b*NPT+n)*3+1];
    float x2 = pts[((size_t)b*NPT+n)*3+2];
    float y0 = T[0]*x0 + T[1]*x1 + T[2]*x2 + T[3];
    float y1 = T[4]*x0 + T[5]*x1 + T[6]*x2 + T[7];
    float y2 = T[8]*x0 + T[9]*x1 + T[10]*x2 + T[11];
    g_pto[idx] = make_float4(y0, y1, y2, y0*y0+y1*y1+y2*y2);

#define HUBER(d) ((d) > THRESH ? (d) - 0.5f*THRESH : (d)*(d)*(0.5f/THRESH))
    float d0 = fabsf(px-y0), d1 = fabsf(py-y1), d2 = fabsf(pz-y2);
    float corr = HUBER(d0) + HUBER(d1) + HUBER(d2);
#undef HUBER

    float v = block_sum(e2p, rsm);
    if (threadIdx.x == 0) atomicAdd(&g_acc[2], (double)v);
    __syncthreads();
    v = block_sum(gq, rsm);
    if (threadIdx.x == 0) atomicAdd(&g_acc[3], (double)v);
    __syncthreads();
    v = block_sum(corr, rsm);
    if (threadIdx.x == 0) atomicAdd(&g_acc[1], (double)v);
}

// ------------------------- pass 2: column-parallel ---------------------------
// grid 2048: bx -> rq(32 row-chunks of 32 rows) x b(32) x mat(2).
// 256 threads, each owns 4 full columns for its 32-row chunk; merge via atomics.
__global__ __launch_bounds__(256)
void k_pass2(const float* __restrict__ A1, const float* __restrict__ A2) {
    __shared__ float isr[32];
    int bx = blockIdx.x;
    int rq = bx & 31; int b = (bx >> 5) & 31; int mat = bx >> 10;
    int tid = threadIdx.x;
    int row0 = rq * 32;
    if (tid < 32)
        isr[tid] = g_invSr[(size_t)(mat*BSZ + b)*NPT + row0 + tid];
    __syncthreads();

    const float* A = (mat ? A2 : A1) + (size_t)b*NPT*NPT + (size_t)row0*NPT + tid*4;

    float sc0=0,sc1=0,sc2=0,sc3=0, c0=0,c1=0,c2=0,c3=0;
#pragma unroll 8
    for (int r = 0; r < 32; r++) {
        float4 a = __ldcs((const float4*)(A + (size_t)r*NPT));
        float w = isr[r];
        float e;
        e=__expf(a.x); sc0+=e; c0=fmaf(e,w,c0);
        e=__expf(a.y); sc1+=e; c1=fmaf(e,w,c1);
        e=__expf(a.z); sc2+=e; c2=fmaf(e,w,c2);
        e=__expf(a.w); sc3+=e; c3=fmaf(e,w,c3);
    }
    size_t o = (size_t)(mat*BSZ + b)*NPT + tid*4;
    atomicAdd(&g_Sc[o+0], sc0); atomicAdd(&g_Sc[o+1], sc1);
    atomicAdd(&g_Sc[o+2], sc2); atomicAdd(&g_Sc[o+3], sc3);
    atomicAdd(&g_C[o+0], c0);  atomicAdd(&g_C[o+1], c1);
    atomicAdd(&g_C[o+2], c2);  atomicAdd(&g_C[o+3], c3);
}

// ------------------------- column finalize -----------------------------------
__global__ __launch_bounds__(256)
void k_colfinal() {
    __shared__ float rsm[32];
    int i = blockIdx.x * 256 + threadIdx.x;   // < 65536
    float v = __logf(g_Sc[i]) * g_C[i];
    v = block_sum(v, rsm);
    if (threadIdx.x == 0) atomicAdd(&g_acc[4], (double)v);
}

// ------------------------- chamfer (packed f32x2) ----------------------------
// grid 128: bx -> b(32) x dir(2) x prob(2). 512 threads, 2 x-points each.
__global__ __launch_bounds__(512)
void k_chamfer() {
    __shared__ ulonglong2 sYA[NPT/2];   // (x-pair, y-pair)
    __shared__ ulonglong2 sYB[NPT/2];   // (z-pair, w-pair)
    __shared__ float rsm[32];
    int bx = blockIdx.x;
    int b = bx & 31; int dir = (bx >> 5) & 1; int prob = bx >> 6;
    size_t base = (size_t)(prob*BSZ + b) * NPT;
    const float4* X = dir ? (g_pin + base) : (g_pto + base);
    const float4* Y = dir ? (g_pto + base) : (g_pin + base);
    int tid = threadIdx.x;

    {
        float4 y0 = Y[2*tid], y1 = Y[2*tid+1];
        sYA[tid] = make_ulonglong2(pk2(y0.x, y1.x), pk2(y0.y, y1.y));
        sYB[tid] = make_ulonglong2(pk2(y0.z, y1.z), pk2(y0.w, y1.w));
    }
    __syncthreads();

    float4 xa = X[tid];
    float4 xb = X[tid + 512];
    unsigned long long ax = pk2(xa.x, xa.x), ay = pk2(xa.y, xa.y), az = pk2(xa.z, xa.z);
    unsigned long long bx2 = pk2(xb.x, xb.x), by = pk2(xb.y, xb.y), bz = pk2(xb.z, xb.z);
    const unsigned long long neg2 = pk2(-2.f, -2.f);

    float mna = 1e30f, mnb = 1e30f;
#pragma unroll 4
    for (int m = 0; m < NPT/2; m++) {
        ulonglong2 A = sYA[m];
        ulonglong2 B = sYB[m];
        unsigned long long d, v;
        float lo, hi;
        d = mul2(ax, A.x); d = fma2(ay, A.y, d); d = fma2(az, B.x, d);
        v = fma2(neg2, d, B.y);
        upk2(v, lo, hi);
        mna = fminf(mna, fminf(lo, hi));
        d = mul2(bx2, A.x); d = fma2(by, A.y, d); d = fma2(bz, B.x, d);
        v = fma2(neg2, d, B.y);
        upk2(v, lo, hi);
        mnb = fminf(mnb, fminf(lo, hi));
    }
    float dsum = fmaxf(xa.w + mna, 0.f) + fmaxf(xb.w + mnb, 0.f);
    float v = block_sum(dsum, rsm);
    if (tid == 0) atomicAdd(&g_acc[0], (double)v);
}

// ------------------------- final combine -------------------------------------
__global__ void k_final(float* __restrict__ out) {
    int b = threadIdx.x;   // 32 threads
    float n1 = sqrtf(g_ssq1[b]);
    float n2 = sqrtf(g_ssq2[b]);
    float cosv = 1.f - g_dot[b] / (fmaxf(n1, 1e-8f) * fmaxf(n2, 1e-8f));
    cosv = wsum(cosv);
    if (b == 0) {
        double invBN = 1.0 / (double)(BSZ * NPT);
        double total = g_acc[0] * invBN
                     + g_acc[1] * invBN
                     + ENT_WT * invBN * (g_acc[2] + g_acc[4] - g_acc[3])
                     + (double)cosv / (double)BSZ;
        out[0] = (float)total;
    }
}

// ------------------------- launch --------------------------------------------
extern "C" void kernel_launch(void* const* d_in, const int* in_sizes, int n_in,
                              void* d_out, int out_size) {
    const float* P1 = (const float*)d_in[0];
    const float* P2 = (const float*)d_in[1];
    const float* A1 = (const float*)d_in[2];
    const float* A2 = (const float*)d_in[3];
    const float* sc = (const float*)d_in[4];
    const float* rt = (const float*)d_in[5];
    const float* tr = (const float*)d_in[6];
    float* out = (float*)d_out;

    k_init<<<TOT/256, 256>>>(sc, rt, tr);
    k_pass1<<<dim3(BSZ, 64), 256>>>(A1, A2, P1, P2);
    k_rowfinal<<<TOT/256, 256>>>(P1, P2);
    k_pass2<<<2048, 256>>>(A1, A2);
    k_colfinal<<<TOT/256, 256>>>();
    k_chamfer<<<128, 512>>>();
    k_final<<<1, 32>>>(out);
}